// round 1
// baseline (speedup 1.0000x reference)
#include <cuda_runtime.h>

#define NA 50000
#define NP 100000
#define DA 512
#define DP 256
#define HH 64
#define NOUT 16
#define NHOP 3
#define EMAX 2000000

// ------------------------- device scratch (static; no allocs) ----------------
__device__ float g_xa[NA * HH];
__device__ float g_xp[NP * HH];
__device__ float g_haA[NA * HH];
__device__ float g_haB[NA * HH];
__device__ float g_hpA[NP * HH];
__device__ float g_hpB[NP * HH];

__device__ int g_deg_ap[NA];
__device__ int g_rp_ap[NA + 1];
__device__ int g_cur_ap[NA];
__device__ int g_ct_ap[EMAX];

__device__ int g_deg_pa[NP];
__device__ int g_rp_pa[NP + 1];
__device__ int g_cur_pa[NP];
__device__ int g_ct_pa[EMAX];

__device__ int g_deg_pp[NP];
__device__ int g_rp_pp[NP + 1];
__device__ int g_cur_pp[NP];
__device__ int g_ct_pp[EMAX];

__device__ float g_x1_ap[NA], g_w2_ap[NA], g_h1_ap[NP];
__device__ float g_x1_pa[NP], g_w2_pa[NP], g_h1_pa[NA];
__device__ float g_x1_pp[NP], g_w2_pp[NP], g_h1_pp[NP];

// ------------------------- input projection GEMM -----------------------------
// C[M x 64] = relu(A[M x K] @ W[K x 64] + b), K % 16 == 0
__global__ void proj_kernel(const float* __restrict__ A, const float* __restrict__ W,
                            const float* __restrict__ b, float* __restrict__ C,
                            int M, int K) {
    __shared__ __align__(16) float As[16][68];
    __shared__ __align__(16) float Ws[16][64];
    int tx = threadIdx.x;              // 256 threads
    int tr = tx >> 4, tc = tx & 15;    // 16x16 thread grid, 4x4 per thread
    float acc[4][4];
#pragma unroll
    for (int i = 0; i < 4; i++)
#pragma unroll
        for (int j = 0; j < 4; j++) acc[i][j] = 0.f;

    int rowBase = blockIdx.x * 64;
    for (int k0 = 0; k0 < K; k0 += 16) {
#pragma unroll
        for (int i = tx; i < 64 * 16; i += 256) {
            int r = i >> 4, c = i & 15;
            int gr = rowBase + r;
            As[c][r] = (gr < M) ? A[(size_t)gr * K + (k0 + c)] : 0.f;
        }
#pragma unroll
        for (int i = tx; i < 16 * 64; i += 256) {
            int r = i >> 6, c = i & 63;
            Ws[r][c] = W[(size_t)(k0 + r) * 64 + c];
        }
        __syncthreads();
#pragma unroll
        for (int kk = 0; kk < 16; kk++) {
            float4 av = *reinterpret_cast<const float4*>(&As[kk][tr * 4]);
            float4 wv = *reinterpret_cast<const float4*>(&Ws[kk][tc * 4]);
            acc[0][0] += av.x * wv.x; acc[0][1] += av.x * wv.y; acc[0][2] += av.x * wv.z; acc[0][3] += av.x * wv.w;
            acc[1][0] += av.y * wv.x; acc[1][1] += av.y * wv.y; acc[1][2] += av.y * wv.z; acc[1][3] += av.y * wv.w;
            acc[2][0] += av.z * wv.x; acc[2][1] += av.z * wv.y; acc[2][2] += av.z * wv.z; acc[2][3] += av.z * wv.w;
            acc[3][0] += av.w * wv.x; acc[3][1] += av.w * wv.y; acc[3][2] += av.w * wv.z; acc[3][3] += av.w * wv.w;
        }
        __syncthreads();
    }
#pragma unroll
    for (int i = 0; i < 4; i++) {
        int gr = rowBase + tr * 4 + i;
        if (gr < M) {
#pragma unroll
            for (int j = 0; j < 4; j++) {
                float v = acc[i][j] + b[tc * 4 + j];
                C[(size_t)gr * 64 + tc * 4 + j] = v > 0.f ? v : 0.f;
            }
        }
    }
}

// ------------------------- CSR build ----------------------------------------
__global__ void zero_deg_kernel() {
    int i = blockIdx.x * blockDim.x + threadIdx.x;
    if (i < NA) g_deg_ap[i] = 0;
    if (i < NP) { g_deg_pa[i] = 0; g_deg_pp[i] = 0; }
}

__global__ void hist_kernel(const int* __restrict__ s, int E, int* __restrict__ deg) {
    int i = blockIdx.x * blockDim.x + threadIdx.x;
    if (i < E) atomicAdd(&deg[s[i]], 1);
}

__global__ void scan_kernel(const int* __restrict__ deg, int* __restrict__ rp,
                            int* __restrict__ cur, int n) {
    __shared__ int carry;
    __shared__ int wsum[32];
    if (threadIdx.x == 0) carry = 0;
    __syncthreads();
    int lane = threadIdx.x & 31, wid = threadIdx.x >> 5;
    for (int base = 0; base < n; base += 1024) {
        int i = base + threadIdx.x;
        int v = (i < n) ? deg[i] : 0;
        int x = v;
#pragma unroll
        for (int o = 1; o < 32; o <<= 1) {
            int y = __shfl_up_sync(0xffffffffu, x, o);
            if (lane >= o) x += y;
        }
        if (lane == 31) wsum[wid] = x;
        __syncthreads();
        if (wid == 0) {
            int sv = wsum[lane];
#pragma unroll
            for (int o = 1; o < 32; o <<= 1) {
                int y = __shfl_up_sync(0xffffffffu, sv, o);
                if (lane >= o) sv += y;
            }
            wsum[lane] = sv;
        }
        __syncthreads();
        int excl = carry + x - v + ((wid > 0) ? wsum[wid - 1] : 0);
        if (i < n) { rp[i] = excl; cur[i] = excl; }
        int tot = wsum[31];
        __syncthreads();
        if (threadIdx.x == 0) carry += tot;
        __syncthreads();
    }
    if (threadIdx.x == 0) rp[n] = carry;
}

__global__ void scatter_kernel(const int* __restrict__ s, const int* __restrict__ t, int E,
                               int* __restrict__ cur, int* __restrict__ ct) {
    int i = blockIdx.x * blockDim.x + threadIdx.x;
    if (i < E) {
        int pos = atomicAdd(&cur[s[i]], 1);
        ct[pos] = t[i];
    }
}

// ------------------------- per-node scalar precompute ------------------------
// x1[n] = x[n]·a1 ; w2[n] = exp(lrelu(x1[n] + x[n]·a2))
__global__ void src_scalar_kernel(const float* __restrict__ x,
                                  const float* __restrict__ a1, const float* __restrict__ a2,
                                  float* __restrict__ x1o, float* __restrict__ w2o, int n) {
    int w = (blockIdx.x * blockDim.x + threadIdx.x) >> 5;
    int lane = threadIdx.x & 31;
    if (w >= n) return;
    const float* xr = x + (size_t)w * HH;
    float v0 = xr[lane], v1 = xr[lane + 32];
    float s1 = v0 * a1[lane] + v1 * a1[lane + 32];
    float s2 = v0 * a2[lane] + v1 * a2[lane + 32];
#pragma unroll
    for (int o = 16; o; o >>= 1) {
        s1 += __shfl_xor_sync(0xffffffffu, s1, o);
        s2 += __shfl_xor_sync(0xffffffffu, s2, o);
    }
    if (lane == 0) {
        x1o[w] = s1;
        float z = s1 + s2;
        z = z >= 0.f ? z : 0.2f * z;
        w2o[w] = expf(z);
    }
}

// h1[n] = h[n]·a2
__global__ void tgt_scalar_kernel(const float* __restrict__ h, const float* __restrict__ a2,
                                  float* __restrict__ h1o, int n) {
    int w = (blockIdx.x * blockDim.x + threadIdx.x) >> 5;
    int lane = threadIdx.x & 31;
    if (w >= n) return;
    const float* hr = h + (size_t)w * HH;
    float s = hr[lane] * a2[lane] + hr[lane + 32] * a2[lane + 32];
#pragma unroll
    for (int o = 16; o; o >>= 1) s += __shfl_xor_sync(0xffffffffu, s, o);
    if (lane == 0) h1o[w] = s;
}

// ------------------------- aggregation --------------------------------------
__device__ __forceinline__ float eluf(float v) { return v > 0.f ? v : expm1f(v); }

// One relation's edge accumulation for one source node (warp-cooperative).
__device__ __forceinline__ void agg_rel(int lane, int beg, int end,
                                        const int* __restrict__ ct,
                                        const float* __restrict__ ht,
                                        float x1s, const float* __restrict__ h1,
                                        float& acc0, float& acc1, float& wsum) {
    for (int j0 = beg; j0 < end; j0 += 32) {
        int j = j0 + lane;
        float wv = 0.f;
        int t = 0;
        if (j < end) {
            t = ct[j];
            float z = x1s + h1[t];
            z = z >= 0.f ? z : 0.2f * z;
            wv = expf(z);
            wsum += wv;
        }
        int cnt = min(32, end - j0);
#pragma unroll 4
        for (int k = 0; k < cnt; k++) {
            float wk = __shfl_sync(0xffffffffu, wv, k);
            int tk = __shfl_sync(0xffffffffu, t, k);
            const float* hr = ht + (size_t)tk * HH;
            acc0 += wk * hr[lane];
            acc1 += wk * hr[lane + 32];
        }
    }
}

__global__ void agg_a_kernel(const int* __restrict__ rp, const int* __restrict__ ct,
                             const float* __restrict__ x, const float* __restrict__ ht,
                             const float* __restrict__ x1, const float* __restrict__ h1,
                             const float* __restrict__ w2,
                             float* __restrict__ out, int n) {
    int wrp = (blockIdx.x * blockDim.x + threadIdx.x) >> 5;
    if (wrp >= n) return;
    int lane = threadIdx.x & 31;
    float x1s = x1[wrp];
    int beg = rp[wrp], end = rp[wrp + 1];
    float acc0 = 0.f, acc1 = 0.f, wsum = 0.f;
    agg_rel(lane, beg, end, ct, ht, x1s, h1, acc0, acc1, wsum);
#pragma unroll
    for (int o = 16; o; o >>= 1) wsum += __shfl_xor_sync(0xffffffffu, wsum, o);
    float w2s = w2[wrp];
    float inv = 1.f / (wsum + w2s);
    const float* xr = x + (size_t)wrp * HH;
    float v0 = (acc0 + w2s * xr[lane]) * inv;
    float v1 = (acc1 + w2s * xr[lane + 32]) * inv;
    out[(size_t)wrp * HH + lane] = eluf(v0);
    out[(size_t)wrp * HH + lane + 32] = eluf(v1);
}

__global__ void agg_p_kernel(const int* __restrict__ rp1, const int* __restrict__ ct1,
                             const int* __restrict__ rp2, const int* __restrict__ ct2,
                             const float* __restrict__ xp,
                             const float* __restrict__ ha, const float* __restrict__ hp,
                             const float* __restrict__ x1_1, const float* __restrict__ h1_1,
                             const float* __restrict__ w2_1,
                             const float* __restrict__ x1_2, const float* __restrict__ h1_2,
                             const float* __restrict__ w2_2,
                             float* __restrict__ out, int n) {
    int wrp = (blockIdx.x * blockDim.x + threadIdx.x) >> 5;
    if (wrp >= n) return;
    int lane = threadIdx.x & 31;
    const float* xr = xp + (size_t)wrp * HH;
    float xv0 = xr[lane], xv1 = xr[lane + 32];

    // relation p->a (gathers h_a)
    float a0 = 0.f, a1v = 0.f, ws1 = 0.f;
    agg_rel(lane, rp1[wrp], rp1[wrp + 1], ct1, ha, x1_1[wrp], h1_1, a0, a1v, ws1);
#pragma unroll
    for (int o = 16; o; o >>= 1) ws1 += __shfl_xor_sync(0xffffffffu, ws1, o);
    float w2a = w2_1[wrp];
    float inv1 = 1.f / (ws1 + w2a);
    float r10 = (a0 + w2a * xv0) * inv1;
    float r11 = (a1v + w2a * xv1) * inv1;

    // relation p->p (gathers h_p)
    float b0 = 0.f, b1v = 0.f, ws2 = 0.f;
    agg_rel(lane, rp2[wrp], rp2[wrp + 1], ct2, hp, x1_2[wrp], h1_2, b0, b1v, ws2);
#pragma unroll
    for (int o = 16; o; o >>= 1) ws2 += __shfl_xor_sync(0xffffffffu, ws2, o);
    float w2b = w2_2[wrp];
    float inv2 = 1.f / (ws2 + w2b);
    float r20 = (b0 + w2b * xv0) * inv2;
    float r21 = (b1v + w2b * xv1) * inv2;

    out[(size_t)wrp * HH + lane] = eluf(0.5f * (r10 + r20));
    out[(size_t)wrp * HH + lane + 32] = eluf(0.5f * (r11 + r21));
}

// ------------------------- output projection ---------------------------------
__global__ void fc2_kernel(const float* __restrict__ h, const float* __restrict__ W,
                           const float* __restrict__ b, float* __restrict__ out, int n) {
    __shared__ float Ws[HH * NOUT];
    __shared__ float bs[NOUT];
    for (int i = threadIdx.x; i < HH * NOUT; i += blockDim.x) Ws[i] = W[i];
    if (threadIdx.x < NOUT) bs[threadIdx.x] = b[threadIdx.x];
    __syncthreads();
    int idx = blockIdx.x * blockDim.x + threadIdx.x;
    int node = idx >> 4, col = idx & 15;
    if (node >= n) return;
    const float* hr = h + (size_t)node * HH;
    float s = bs[col];
#pragma unroll
    for (int k = 0; k < HH; k++) s += hr[k] * Ws[k * NOUT + col];
    out[(size_t)node * NOUT + col] = s;
}

// ------------------------- host orchestration --------------------------------
extern "C" void kernel_launch(void* const* d_in, const int* in_sizes, int n_in,
                              void* d_out, int out_size) {
    const float* x_a = (const float*)d_in[0];
    const float* x_p = (const float*)d_in[1];
    const int* ap_s = (const int*)d_in[2];
    const int* ap_t = (const int*)d_in[3];
    const int* pa_s = (const int*)d_in[4];
    const int* pa_t = (const int*)d_in[5];
    const int* pp_s = (const int*)d_in[6];
    const int* pp_t = (const int*)d_in[7];
    const float* fc1_a_w = (const float*)d_in[8];
    const float* fc1_a_b = (const float*)d_in[9];
    const float* fc1_p_w = (const float*)d_in[10];
    const float* fc1_p_b = (const float*)d_in[11];
    const float* fc2_w = (const float*)d_in[12];
    const float* fc2_b = (const float*)d_in[13];
    const float* a1_ap = (const float*)d_in[14];
    const float* a2_ap = (const float*)d_in[15];
    const float* a1_pa = (const float*)d_in[16];
    const float* a2_pa = (const float*)d_in[17];
    const float* a1_pp = (const float*)d_in[18];
    const float* a2_pp = (const float*)d_in[19];
    float* out = (float*)d_out;

    int E_ap = in_sizes[2], E_pa = in_sizes[4], E_pp = in_sizes[6];
    if (E_ap > EMAX) E_ap = EMAX;
    if (E_pa > EMAX) E_pa = EMAX;
    if (E_pp > EMAX) E_pp = EMAX;

    float *xa, *xp, *haA, *haB, *hpA, *hpB;
    cudaGetSymbolAddress((void**)&xa, g_xa);
    cudaGetSymbolAddress((void**)&xp, g_xp);
    cudaGetSymbolAddress((void**)&haA, g_haA);
    cudaGetSymbolAddress((void**)&haB, g_haB);
    cudaGetSymbolAddress((void**)&hpA, g_hpA);
    cudaGetSymbolAddress((void**)&hpB, g_hpB);

    int *deg_ap, *rp_ap, *cur_ap, *ct_ap;
    int *deg_pa, *rp_pa, *cur_pa, *ct_pa;
    int *deg_pp, *rp_pp, *cur_pp, *ct_pp;
    cudaGetSymbolAddress((void**)&deg_ap, g_deg_ap);
    cudaGetSymbolAddress((void**)&rp_ap, g_rp_ap);
    cudaGetSymbolAddress((void**)&cur_ap, g_cur_ap);
    cudaGetSymbolAddress((void**)&ct_ap, g_ct_ap);
    cudaGetSymbolAddress((void**)&deg_pa, g_deg_pa);
    cudaGetSymbolAddress((void**)&rp_pa, g_rp_pa);
    cudaGetSymbolAddress((void**)&cur_pa, g_cur_pa);
    cudaGetSymbolAddress((void**)&ct_pa, g_ct_pa);
    cudaGetSymbolAddress((void**)&deg_pp, g_deg_pp);
    cudaGetSymbolAddress((void**)&rp_pp, g_rp_pp);
    cudaGetSymbolAddress((void**)&cur_pp, g_cur_pp);
    cudaGetSymbolAddress((void**)&ct_pp, g_ct_pp);

    float *x1_ap, *w2_ap, *h1_ap, *x1_pa, *w2_pa, *h1_pa, *x1_pp, *w2_pp, *h1_pp;
    cudaGetSymbolAddress((void**)&x1_ap, g_x1_ap);
    cudaGetSymbolAddress((void**)&w2_ap, g_w2_ap);
    cudaGetSymbolAddress((void**)&h1_ap, g_h1_ap);
    cudaGetSymbolAddress((void**)&x1_pa, g_x1_pa);
    cudaGetSymbolAddress((void**)&w2_pa, g_w2_pa);
    cudaGetSymbolAddress((void**)&h1_pa, g_h1_pa);
    cudaGetSymbolAddress((void**)&x1_pp, g_x1_pp);
    cudaGetSymbolAddress((void**)&w2_pp, g_w2_pp);
    cudaGetSymbolAddress((void**)&h1_pp, g_h1_pp);

    // 1) input projections
    proj_kernel<<<(NA + 63) / 64, 256>>>(x_a, fc1_a_w, fc1_a_b, xa, NA, DA);
    proj_kernel<<<(NP + 63) / 64, 256>>>(x_p, fc1_p_w, fc1_p_b, xp, NP, DP);

    // 2) CSR build (by source), shared across all 3 hops
    zero_deg_kernel<<<(NP + 255) / 256, 256>>>();
    hist_kernel<<<(E_ap + 255) / 256, 256>>>(ap_s, E_ap, deg_ap);
    hist_kernel<<<(E_pa + 255) / 256, 256>>>(pa_s, E_pa, deg_pa);
    hist_kernel<<<(E_pp + 255) / 256, 256>>>(pp_s, E_pp, deg_pp);
    scan_kernel<<<1, 1024>>>(deg_ap, rp_ap, cur_ap, NA);
    scan_kernel<<<1, 1024>>>(deg_pa, rp_pa, cur_pa, NP);
    scan_kernel<<<1, 1024>>>(deg_pp, rp_pp, cur_pp, NP);
    scatter_kernel<<<(E_ap + 255) / 256, 256>>>(ap_s, ap_t, E_ap, cur_ap, ct_ap);
    scatter_kernel<<<(E_pa + 255) / 256, 256>>>(pa_s, pa_t, E_pa, cur_pa, ct_pa);
    scatter_kernel<<<(E_pp + 255) / 256, 256>>>(pp_s, pp_t, E_pp, cur_pp, ct_pp);

    // 3) hops
    const float* ha = xa;
    const float* hp = xp;
    const int WB = 8;  // warps per 256-thread block
    for (int i = 0; i < NHOP; i++) {
        float* hao = (i & 1) ? haB : haA;
        float* hpo = (i & 1) ? hpB : hpA;
        const float* v1ap = a1_ap + i * HH; const float* v2ap = a2_ap + i * HH;
        const float* v1pa = a1_pa + i * HH; const float* v2pa = a2_pa + i * HH;
        const float* v1pp = a1_pp + i * HH; const float* v2pp = a2_pp + i * HH;

        src_scalar_kernel<<<(NA + WB - 1) / WB, 256>>>(xa, v1ap, v2ap, x1_ap, w2_ap, NA);
        tgt_scalar_kernel<<<(NP + WB - 1) / WB, 256>>>(hp, v2ap, h1_ap, NP);
        src_scalar_kernel<<<(NP + WB - 1) / WB, 256>>>(xp, v1pa, v2pa, x1_pa, w2_pa, NP);
        tgt_scalar_kernel<<<(NA + WB - 1) / WB, 256>>>(ha, v2pa, h1_pa, NA);
        src_scalar_kernel<<<(NP + WB - 1) / WB, 256>>>(xp, v1pp, v2pp, x1_pp, w2_pp, NP);
        tgt_scalar_kernel<<<(NP + WB - 1) / WB, 256>>>(hp, v2pp, h1_pp, NP);

        agg_a_kernel<<<(NA + WB - 1) / WB, 256>>>(rp_ap, ct_ap, xa, hp,
                                                  x1_ap, h1_ap, w2_ap, hao, NA);
        agg_p_kernel<<<(NP + WB - 1) / WB, 256>>>(rp_pa, ct_pa, rp_pp, ct_pp, xp, ha, hp,
                                                  x1_pa, h1_pa, w2_pa,
                                                  x1_pp, h1_pp, w2_pp, hpo, NP);
        ha = hao;
        hp = hpo;
    }

    // 4) output projection
    fc2_kernel<<<(NA * NOUT + 255) / 256, 256>>>(ha, fc2_w, fc2_b, out, NA);
}

// round 2
// speedup vs baseline: 1.1389x; 1.1389x over previous
#include <cuda_runtime.h>

#define NA 50000
#define NP 100000
#define DA 512
#define DP 256
#define HH 64
#define NOUT 16
#define NHOP 3
#define EMAX 2000000

// ------------------------- device scratch (static; no allocs) ----------------
__device__ float g_xa[NA * HH];
__device__ float g_xp[NP * HH];
__device__ float g_haA[NA * HH];
__device__ float g_haB[NA * HH];
__device__ float g_hpA[NP * HH];
__device__ float g_hpB[NP * HH];

__device__ int g_deg_ap[NA];
__device__ int g_rp_ap[NA + 1];
__device__ int g_cur_ap[NA];
__device__ int g_ct_ap[EMAX];

__device__ int g_deg_pa[NP];
__device__ int g_rp_pa[NP + 1];
__device__ int g_cur_pa[NP];
__device__ int g_ct_pa[EMAX];

__device__ int g_deg_pp[NP];
__device__ int g_rp_pp[NP + 1];
__device__ int g_cur_pp[NP];
__device__ int g_ct_pp[EMAX];

// per-hop source-side scalars precomputed for ALL hops at once
__device__ float g_x1_ap[NHOP * NA], g_w2_ap[NHOP * NA];
__device__ float g_x1_pa[NHOP * NP], g_w2_pa[NHOP * NP];
__device__ float g_x1_pp[NHOP * NP], g_w2_pp[NHOP * NP];
// target-side scalars, recomputed each hop
__device__ float g_h1_ap[NP], g_h1_pa[NA], g_h1_pp[NP];

// ------------------------- input projection GEMM -----------------------------
// C[M x 64] = relu(A[M x K] @ W[K x 64] + b), K % 16 == 0
__global__ void proj_kernel(const float* __restrict__ A, const float* __restrict__ W,
                            const float* __restrict__ b, float* __restrict__ C,
                            int M, int K) {
    __shared__ __align__(16) float As[16][68];
    __shared__ __align__(16) float Ws[16][64];
    int tx = threadIdx.x;              // 256 threads
    int tr = tx >> 4, tc = tx & 15;    // 16x16 thread grid, 4x4 per thread
    float acc[4][4];
#pragma unroll
    for (int i = 0; i < 4; i++)
#pragma unroll
        for (int j = 0; j < 4; j++) acc[i][j] = 0.f;

    int rowBase = blockIdx.x * 64;
    for (int k0 = 0; k0 < K; k0 += 16) {
#pragma unroll
        for (int i = tx; i < 64 * 16; i += 256) {
            int r = i >> 4, c = i & 15;
            int gr = rowBase + r;
            As[c][r] = (gr < M) ? A[(size_t)gr * K + (k0 + c)] : 0.f;
        }
#pragma unroll
        for (int i = tx; i < 16 * 64; i += 256) {
            int r = i >> 6, c = i & 63;
            Ws[r][c] = W[(size_t)(k0 + r) * 64 + c];
        }
        __syncthreads();
#pragma unroll
        for (int kk = 0; kk < 16; kk++) {
            float4 av = *reinterpret_cast<const float4*>(&As[kk][tr * 4]);
            float4 wv = *reinterpret_cast<const float4*>(&Ws[kk][tc * 4]);
            acc[0][0] += av.x * wv.x; acc[0][1] += av.x * wv.y; acc[0][2] += av.x * wv.z; acc[0][3] += av.x * wv.w;
            acc[1][0] += av.y * wv.x; acc[1][1] += av.y * wv.y; acc[1][2] += av.y * wv.z; acc[1][3] += av.y * wv.w;
            acc[2][0] += av.z * wv.x; acc[2][1] += av.z * wv.y; acc[2][2] += av.z * wv.z; acc[2][3] += av.z * wv.w;
            acc[3][0] += av.w * wv.x; acc[3][1] += av.w * wv.y; acc[3][2] += av.w * wv.z; acc[3][3] += av.w * wv.w;
        }
        __syncthreads();
    }
#pragma unroll
    for (int i = 0; i < 4; i++) {
        int gr = rowBase + tr * 4 + i;
        if (gr < M) {
#pragma unroll
            for (int j = 0; j < 4; j++) {
                float v = acc[i][j] + b[tc * 4 + j];
                C[(size_t)gr * 64 + tc * 4 + j] = v > 0.f ? v : 0.f;
            }
        }
    }
}

// ------------------------- CSR build ----------------------------------------
__global__ void zero_deg_kernel() {
    int i = blockIdx.x * blockDim.x + threadIdx.x;
    if (i < NA) g_deg_ap[i] = 0;
    if (i < NP) { g_deg_pa[i] = 0; g_deg_pp[i] = 0; }
}

__global__ void hist_all_kernel(const int* __restrict__ s_ap, const int* __restrict__ s_pa,
                                const int* __restrict__ s_pp, int Eap, int Epa, int Epp) {
    int i = blockIdx.x * blockDim.x + threadIdx.x;
    int tot = Eap + Epa + Epp;
    if (i >= tot) return;
    if (i < Eap) atomicAdd(&g_deg_ap[s_ap[i]], 1);
    else if (i < Eap + Epa) atomicAdd(&g_deg_pa[s_pa[i - Eap]], 1);
    else atomicAdd(&g_deg_pp[s_pp[i - Eap - Epa]], 1);
}

__device__ void scan_block(const int* __restrict__ deg, int* __restrict__ rp,
                           int* __restrict__ cur, int n) {
    __shared__ int carry;
    __shared__ int wsum[32];
    if (threadIdx.x == 0) carry = 0;
    __syncthreads();
    int lane = threadIdx.x & 31, wid = threadIdx.x >> 5;
    for (int base = 0; base < n; base += 1024) {
        int i = base + threadIdx.x;
        int v = (i < n) ? deg[i] : 0;
        int x = v;
#pragma unroll
        for (int o = 1; o < 32; o <<= 1) {
            int y = __shfl_up_sync(0xffffffffu, x, o);
            if (lane >= o) x += y;
        }
        if (lane == 31) wsum[wid] = x;
        __syncthreads();
        if (wid == 0) {
            int sv = wsum[lane];
#pragma unroll
            for (int o = 1; o < 32; o <<= 1) {
                int y = __shfl_up_sync(0xffffffffu, sv, o);
                if (lane >= o) sv += y;
            }
            wsum[lane] = sv;
        }
        __syncthreads();
        int excl = carry + x - v + ((wid > 0) ? wsum[wid - 1] : 0);
        if (i < n) { rp[i] = excl; cur[i] = excl; }
        int tot = wsum[31];
        __syncthreads();
        if (threadIdx.x == 0) carry += tot;
        __syncthreads();
    }
    if (threadIdx.x == 0) rp[n] = carry;
}

__global__ void scan_all_kernel() {
    if (blockIdx.x == 0) scan_block(g_deg_ap, g_rp_ap, g_cur_ap, NA);
    else if (blockIdx.x == 1) scan_block(g_deg_pa, g_rp_pa, g_cur_pa, NP);
    else scan_block(g_deg_pp, g_rp_pp, g_cur_pp, NP);
}

__global__ void scatter_all_kernel(const int* __restrict__ s_ap, const int* __restrict__ t_ap,
                                   const int* __restrict__ s_pa, const int* __restrict__ t_pa,
                                   const int* __restrict__ s_pp, const int* __restrict__ t_pp,
                                   int Eap, int Epa, int Epp) {
    int i = blockIdx.x * blockDim.x + threadIdx.x;
    int tot = Eap + Epa + Epp;
    if (i >= tot) return;
    if (i < Eap) {
        int pos = atomicAdd(&g_cur_ap[s_ap[i]], 1);
        g_ct_ap[pos] = t_ap[i];
    } else if (i < Eap + Epa) {
        int j = i - Eap;
        int pos = atomicAdd(&g_cur_pa[s_pa[j]], 1);
        g_ct_pa[pos] = t_pa[j];
    } else {
        int j = i - Eap - Epa;
        int pos = atomicAdd(&g_cur_pp[s_pp[j]], 1);
        g_ct_pp[pos] = t_pp[j];
    }
}

// ------------------------- scalar precompute ---------------------------------
__device__ __forceinline__ float warp_red(float s) {
#pragma unroll
    for (int o = 16; o; o >>= 1) s += __shfl_xor_sync(0xffffffffu, s, o);
    return s;
}

// source-side x1/w2 for all hops, both node types (x is fixed per hop)
__global__ void src_all_kernel(const float* __restrict__ xa, const float* __restrict__ xp,
                               const float* __restrict__ a1ap, const float* __restrict__ a2ap,
                               const float* __restrict__ a1pa, const float* __restrict__ a2pa,
                               const float* __restrict__ a1pp, const float* __restrict__ a2pp) {
    int w = (blockIdx.x * blockDim.x + threadIdx.x) >> 5;
    int lane = threadIdx.x & 31;
    if (w < NA) {
        const float* xr = xa + (size_t)w * HH;
        float v0 = xr[lane], v1 = xr[lane + 32];
#pragma unroll
        for (int i = 0; i < NHOP; i++) {
            float s1 = warp_red(v0 * a1ap[i * HH + lane] + v1 * a1ap[i * HH + lane + 32]);
            float s2 = warp_red(v0 * a2ap[i * HH + lane] + v1 * a2ap[i * HH + lane + 32]);
            if (lane == 0) {
                g_x1_ap[i * NA + w] = s1;
                float z = s1 + s2;
                z = z >= 0.f ? z : 0.2f * z;
                g_w2_ap[i * NA + w] = __expf(z);
            }
        }
    } else if (w < NA + NP) {
        int n = w - NA;
        const float* xr = xp + (size_t)n * HH;
        float v0 = xr[lane], v1 = xr[lane + 32];
#pragma unroll
        for (int i = 0; i < NHOP; i++) {
            float s1 = warp_red(v0 * a1pa[i * HH + lane] + v1 * a1pa[i * HH + lane + 32]);
            float s2 = warp_red(v0 * a2pa[i * HH + lane] + v1 * a2pa[i * HH + lane + 32]);
            float s3 = warp_red(v0 * a1pp[i * HH + lane] + v1 * a1pp[i * HH + lane + 32]);
            float s4 = warp_red(v0 * a2pp[i * HH + lane] + v1 * a2pp[i * HH + lane + 32]);
            if (lane == 0) {
                g_x1_pa[i * NP + n] = s1;
                float z = s1 + s2;
                z = z >= 0.f ? z : 0.2f * z;
                g_w2_pa[i * NP + n] = __expf(z);
                g_x1_pp[i * NP + n] = s3;
                float z2 = s3 + s4;
                z2 = z2 >= 0.f ? z2 : 0.2f * z2;
                g_w2_pp[i * NP + n] = __expf(z2);
            }
        }
    }
}

// target-side h1 for one hop (h changes each hop). hp row read once for ap & pp.
__global__ void tgt_all_kernel(const float* __restrict__ ha, const float* __restrict__ hp,
                               const float* __restrict__ a2ap, const float* __restrict__ a2pa,
                               const float* __restrict__ a2pp) {
    int w = (blockIdx.x * blockDim.x + threadIdx.x) >> 5;
    int lane = threadIdx.x & 31;
    if (w < NP) {
        const float* hr = hp + (size_t)w * HH;
        float v0 = hr[lane], v1 = hr[lane + 32];
        float s1 = warp_red(v0 * a2ap[lane] + v1 * a2ap[lane + 32]);
        float s2 = warp_red(v0 * a2pp[lane] + v1 * a2pp[lane + 32]);
        if (lane == 0) { g_h1_ap[w] = s1; g_h1_pp[w] = s2; }
    } else if (w < NP + NA) {
        int n = w - NP;
        const float* hr = ha + (size_t)n * HH;
        float s = warp_red(hr[lane] * a2pa[lane] + hr[lane + 32] * a2pa[lane + 32]);
        if (lane == 0) g_h1_pa[n] = s;
    }
}

// ------------------------- aggregation --------------------------------------
__device__ __forceinline__ float eluf(float v) { return v > 0.f ? v : expm1f(v); }

// Warp-cooperative accumulation for one relation of one source node.
// float2 gathers (LDG.64), 4 edges per inner iter with 4 independent acc pairs.
__device__ __forceinline__ float2 agg_rel(int lane, int beg, int end,
                                          const int* __restrict__ ct,
                                          const float* __restrict__ ht,
                                          float x1s, const float* __restrict__ h1,
                                          float& wsum) {
    const float2* ht2 = reinterpret_cast<const float2*>(ht);
    float2 a0 = {0.f, 0.f}, a1 = {0.f, 0.f}, a2 = {0.f, 0.f}, a3 = {0.f, 0.f};
    for (int j0 = beg; j0 < end; j0 += 32) {
        int j = j0 + lane;
        float wv = 0.f;
        int t = 0;
        if (j < end) {
            t = ct[j];
            float z = x1s + h1[t];
            z = z >= 0.f ? z : 0.2f * z;
            wv = __expf(z);
            wsum += wv;
        }
        int cnt = min(32, end - j0);
        int k = 0;
        for (; k + 4 <= cnt; k += 4) {
            float w0 = __shfl_sync(0xffffffffu, wv, k);
            float w1 = __shfl_sync(0xffffffffu, wv, k + 1);
            float w2 = __shfl_sync(0xffffffffu, wv, k + 2);
            float w3 = __shfl_sync(0xffffffffu, wv, k + 3);
            int t0 = __shfl_sync(0xffffffffu, t, k);
            int t1 = __shfl_sync(0xffffffffu, t, k + 1);
            int t2 = __shfl_sync(0xffffffffu, t, k + 2);
            int t3 = __shfl_sync(0xffffffffu, t, k + 3);
            float2 v0 = ht2[(size_t)t0 * 32 + lane];
            float2 v1 = ht2[(size_t)t1 * 32 + lane];
            float2 v2 = ht2[(size_t)t2 * 32 + lane];
            float2 v3 = ht2[(size_t)t3 * 32 + lane];
            a0.x += w0 * v0.x; a0.y += w0 * v0.y;
            a1.x += w1 * v1.x; a1.y += w1 * v1.y;
            a2.x += w2 * v2.x; a2.y += w2 * v2.y;
            a3.x += w3 * v3.x; a3.y += w3 * v3.y;
        }
        for (; k < cnt; k++) {
            float wk = __shfl_sync(0xffffffffu, wv, k);
            int tk = __shfl_sync(0xffffffffu, t, k);
            float2 vk = ht2[(size_t)tk * 32 + lane];
            a0.x += wk * vk.x; a0.y += wk * vk.y;
        }
    }
    float2 r;
    r.x = (a0.x + a1.x) + (a2.x + a3.x);
    r.y = (a0.y + a1.y) + (a2.y + a3.y);
    return r;
}

__global__ void __launch_bounds__(256) agg_a_kernel(
        const int* __restrict__ rp, const int* __restrict__ ct,
        const float* __restrict__ x, const float* __restrict__ ht,
        const float* __restrict__ x1, const float* __restrict__ h1,
        const float* __restrict__ w2,
        float* __restrict__ out, int n) {
    int wrp = (blockIdx.x * blockDim.x + threadIdx.x) >> 5;
    if (wrp >= n) return;
    int lane = threadIdx.x & 31;
    float x1s = x1[wrp];
    int beg = rp[wrp], end = rp[wrp + 1];
    float wsum = 0.f;
    float2 acc = agg_rel(lane, beg, end, ct, ht, x1s, h1, wsum);
    wsum = warp_red(wsum);
    float w2s = w2[wrp];
    float inv = 1.f / (wsum + w2s);
    const float2* xr2 = reinterpret_cast<const float2*>(x) + (size_t)wrp * 32;
    float2 xv = xr2[lane];
    float2 o;
    o.x = eluf((acc.x + w2s * xv.x) * inv);
    o.y = eluf((acc.y + w2s * xv.y) * inv);
    reinterpret_cast<float2*>(out)[(size_t)wrp * 32 + lane] = o;
}

__global__ void __launch_bounds__(256) agg_p_kernel(
        const int* __restrict__ rp1, const int* __restrict__ ct1,
        const int* __restrict__ rp2, const int* __restrict__ ct2,
        const float* __restrict__ xp,
        const float* __restrict__ ha, const float* __restrict__ hp,
        const float* __restrict__ x1_1, const float* __restrict__ h1_1,
        const float* __restrict__ w2_1,
        const float* __restrict__ x1_2, const float* __restrict__ h1_2,
        const float* __restrict__ w2_2,
        float* __restrict__ out, int n) {
    int wrp = (blockIdx.x * blockDim.x + threadIdx.x) >> 5;
    if (wrp >= n) return;
    int lane = threadIdx.x & 31;
    const float2* xr2 = reinterpret_cast<const float2*>(xp) + (size_t)wrp * 32;
    float2 xv = xr2[lane];

    float ws1 = 0.f;
    float2 accA = agg_rel(lane, rp1[wrp], rp1[wrp + 1], ct1, ha, x1_1[wrp], h1_1, ws1);
    ws1 = warp_red(ws1);
    float w2a = w2_1[wrp];
    float inv1 = 1.f / (ws1 + w2a);
    float r10 = (accA.x + w2a * xv.x) * inv1;
    float r11 = (accA.y + w2a * xv.y) * inv1;

    float ws2 = 0.f;
    float2 accB = agg_rel(lane, rp2[wrp], rp2[wrp + 1], ct2, hp, x1_2[wrp], h1_2, ws2);
    ws2 = warp_red(ws2);
    float w2b = w2_2[wrp];
    float inv2 = 1.f / (ws2 + w2b);
    float r20 = (accB.x + w2b * xv.x) * inv2;
    float r21 = (accB.y + w2b * xv.y) * inv2;

    float2 o;
    o.x = eluf(0.5f * (r10 + r20));
    o.y = eluf(0.5f * (r11 + r21));
    reinterpret_cast<float2*>(out)[(size_t)wrp * 32 + lane] = o;
}

// ------------------------- output projection ---------------------------------
__global__ void fc2_kernel(const float* __restrict__ h, const float* __restrict__ W,
                           const float* __restrict__ b, float* __restrict__ out, int n) {
    __shared__ float Ws[HH * NOUT];
    __shared__ float bs[NOUT];
    for (int i = threadIdx.x; i < HH * NOUT; i += blockDim.x) Ws[i] = W[i];
    if (threadIdx.x < NOUT) bs[threadIdx.x] = b[threadIdx.x];
    __syncthreads();
    int idx = blockIdx.x * blockDim.x + threadIdx.x;
    int node = idx >> 4, col = idx & 15;
    if (node >= n) return;
    const float* hr = h + (size_t)node * HH;
    float s = bs[col];
#pragma unroll
    for (int k = 0; k < HH; k++) s += hr[k] * Ws[k * NOUT + col];
    out[(size_t)node * NOUT + col] = s;
}

// ------------------------- host orchestration --------------------------------
extern "C" void kernel_launch(void* const* d_in, const int* in_sizes, int n_in,
                              void* d_out, int out_size) {
    const float* x_a = (const float*)d_in[0];
    const float* x_p = (const float*)d_in[1];
    const int* ap_s = (const int*)d_in[2];
    const int* ap_t = (const int*)d_in[3];
    const int* pa_s = (const int*)d_in[4];
    const int* pa_t = (const int*)d_in[5];
    const int* pp_s = (const int*)d_in[6];
    const int* pp_t = (const int*)d_in[7];
    const float* fc1_a_w = (const float*)d_in[8];
    const float* fc1_a_b = (const float*)d_in[9];
    const float* fc1_p_w = (const float*)d_in[10];
    const float* fc1_p_b = (const float*)d_in[11];
    const float* fc2_w = (const float*)d_in[12];
    const float* fc2_b = (const float*)d_in[13];
    const float* a1_ap = (const float*)d_in[14];
    const float* a2_ap = (const float*)d_in[15];
    const float* a1_pa = (const float*)d_in[16];
    const float* a2_pa = (const float*)d_in[17];
    const float* a1_pp = (const float*)d_in[18];
    const float* a2_pp = (const float*)d_in[19];
    float* out = (float*)d_out;

    int E_ap = in_sizes[2], E_pa = in_sizes[4], E_pp = in_sizes[6];
    if (E_ap > EMAX) E_ap = EMAX;
    if (E_pa > EMAX) E_pa = EMAX;
    if (E_pp > EMAX) E_pp = EMAX;
    int E_tot = E_ap + E_pa + E_pp;

    float *xa, *xp, *haA, *haB, *hpA, *hpB;
    cudaGetSymbolAddress((void**)&xa, g_xa);
    cudaGetSymbolAddress((void**)&xp, g_xp);
    cudaGetSymbolAddress((void**)&haA, g_haA);
    cudaGetSymbolAddress((void**)&haB, g_haB);
    cudaGetSymbolAddress((void**)&hpA, g_hpA);
    cudaGetSymbolAddress((void**)&hpB, g_hpB);

    int *rp_ap, *ct_ap, *rp_pa, *ct_pa, *rp_pp, *ct_pp;
    cudaGetSymbolAddress((void**)&rp_ap, g_rp_ap);
    cudaGetSymbolAddress((void**)&ct_ap, g_ct_ap);
    cudaGetSymbolAddress((void**)&rp_pa, g_rp_pa);
    cudaGetSymbolAddress((void**)&ct_pa, g_ct_pa);
    cudaGetSymbolAddress((void**)&rp_pp, g_rp_pp);
    cudaGetSymbolAddress((void**)&ct_pp, g_ct_pp);

    float *x1_ap, *w2_ap, *h1_ap, *x1_pa, *w2_pa, *h1_pa, *x1_pp, *w2_pp, *h1_pp;
    cudaGetSymbolAddress((void**)&x1_ap, g_x1_ap);
    cudaGetSymbolAddress((void**)&w2_ap, g_w2_ap);
    cudaGetSymbolAddress((void**)&h1_ap, g_h1_ap);
    cudaGetSymbolAddress((void**)&x1_pa, g_x1_pa);
    cudaGetSymbolAddress((void**)&w2_pa, g_w2_pa);
    cudaGetSymbolAddress((void**)&h1_pa, g_h1_pa);
    cudaGetSymbolAddress((void**)&x1_pp, g_x1_pp);
    cudaGetSymbolAddress((void**)&w2_pp, g_w2_pp);
    cudaGetSymbolAddress((void**)&h1_pp, g_h1_pp);

    // 1) CSR build (4 launches)
    zero_deg_kernel<<<(NP + 255) / 256, 256>>>();
    hist_all_kernel<<<(E_tot + 255) / 256, 256>>>(ap_s, pa_s, pp_s, E_ap, E_pa, E_pp);
    scan_all_kernel<<<3, 1024>>>();
    scatter_all_kernel<<<(E_tot + 255) / 256, 256>>>(ap_s, ap_t, pa_s, pa_t, pp_s, pp_t,
                                                     E_ap, E_pa, E_pp);

    // 2) input projections (launches #5, #6 — #6 = proj_p gets profiled)
    proj_kernel<<<(NA + 63) / 64, 256>>>(x_a, fc1_a_w, fc1_a_b, xa, NA, DA);
    proj_kernel<<<(NP + 63) / 64, 256>>>(x_p, fc1_p_w, fc1_p_b, xp, NP, DP);

    // 3) source-side scalars for all hops at once
    src_all_kernel<<<((NA + NP) * 32 + 255) / 256, 256>>>(xa, xp, a1_ap, a2_ap,
                                                          a1_pa, a2_pa, a1_pp, a2_pp);

    // 4) hops
    const float* ha = xa;
    const float* hp = xp;
    const int WB = 8;  // warps per 256-thread block
    for (int i = 0; i < NHOP; i++) {
        float* hao = (i & 1) ? haB : haA;
        float* hpo = (i & 1) ? hpB : hpA;

        tgt_all_kernel<<<((NP + NA) * 32 + 255) / 256, 256>>>(ha, hp, a2_ap + i * HH,
                                                              a2_pa + i * HH, a2_pp + i * HH);
        agg_a_kernel<<<(NA + WB - 1) / WB, 256>>>(rp_ap, ct_ap, xa, hp,
                                                  x1_ap + i * NA, h1_ap, w2_ap + i * NA,
                                                  hao, NA);
        agg_p_kernel<<<(NP + WB - 1) / WB, 256>>>(rp_pa, ct_pa, rp_pp, ct_pp, xp, ha, hp,
                                                  x1_pa + i * NP, h1_pa, w2_pa + i * NP,
                                                  x1_pp + i * NP, h1_pp, w2_pp + i * NP,
                                                  hpo, NP);
        ha = hao;
        hp = hpo;
    }

    // 5) output projection
    fc2_kernel<<<(NA * NOUT + 255) / 256, 256>>>(ha, fc2_w, fc2_b, out, NA);
}

// round 3
// speedup vs baseline: 1.3180x; 1.1573x over previous
#include <cuda_runtime.h>
#include <cuda_fp16.h>

#define NA 50000
#define NP 100000
#define DA 512
#define DP 256
#define HH 64
#define NOUT 16
#define NHOP 3
#define EMAX 2000000

// ------------------------- device scratch (static; no allocs) ----------------
__device__ float g_xa[NA * HH];
__device__ float g_xp[NP * HH];
// fp16 gather tables (double-buffered per node type)
__device__ __half g_ha16A[NA * HH];
__device__ __half g_ha16B[NA * HH];
__device__ __half g_hp16A[NP * HH];
__device__ __half g_hp16B[NP * HH];

__device__ int g_deg_ap[NA];
__device__ int g_rp_ap[NA + 1];
__device__ int g_cur_ap[NA];
__device__ int g_ct_ap[EMAX];

__device__ int g_deg_pa[NP];
__device__ int g_rp_pa[NP + 1];
__device__ int g_cur_pa[NP];
__device__ int g_ct_pa[EMAX];

__device__ int g_deg_pp[NP];
__device__ int g_rp_pp[NP + 1];
__device__ int g_cur_pp[NP];
__device__ int g_ct_pp[EMAX];

// per-hop source-side scalars precomputed for ALL hops at once
__device__ float g_x1_ap[NHOP * NA], g_w2_ap[NHOP * NA];
__device__ float g_x1_pa[NHOP * NP], g_w2_pa[NHOP * NP];
__device__ float g_x1_pp[NHOP * NP], g_w2_pp[NHOP * NP];
// target-side scalars, recomputed each hop
__device__ float g_h1_ap[NP], g_h1_pa[NA], g_h1_pp[NP];

// ------------------------- input projection GEMM -----------------------------
// C[M x 64] = relu(A[M x K] @ W[K x 64] + b); also emits fp16 copy.
// 256x64 tile per 256-thread block, 8x8 per thread.
__global__ void __launch_bounds__(256) proj_kernel(
        const float* __restrict__ A, const float* __restrict__ W,
        const float* __restrict__ b, float* __restrict__ C,
        __half2* __restrict__ C16, int M, int K) {
    __shared__ __align__(16) float As[16][260];  // [k][row], pad keeps 16B align
    __shared__ __align__(16) float Ws[16][64];
    int tid = threadIdx.x;
    int r8 = tid >> 3;   // 0..31 -> rows r8*8..r8*8+7
    int c8 = tid & 7;    // 0..7  -> cols c8*8..c8*8+7
    float acc[8][8];
#pragma unroll
    for (int i = 0; i < 8; i++)
#pragma unroll
        for (int j = 0; j < 8; j++) acc[i][j] = 0.f;

    int rowBase = blockIdx.x * 256;
    for (int k0 = 0; k0 < K; k0 += 16) {
        // A tile: 256 rows x 16 k = 1024 float4 loads (4 per thread)
#pragma unroll
        for (int t = 0; t < 4; t++) {
            int i = tid + t * 256;
            int row = i >> 2;
            int kq = (i & 3) * 4;
            float4 v = make_float4(0.f, 0.f, 0.f, 0.f);
            int gr = rowBase + row;
            if (gr < M) v = *reinterpret_cast<const float4*>(&A[(size_t)gr * K + k0 + kq]);
            As[kq + 0][row] = v.x;
            As[kq + 1][row] = v.y;
            As[kq + 2][row] = v.z;
            As[kq + 3][row] = v.w;
        }
        // W tile: 16 x 64 = 1024 floats (4 per thread)
#pragma unroll
        for (int t = 0; t < 4; t++) {
            int i = tid + t * 256;
            Ws[i >> 6][i & 63] = W[(size_t)(k0 + (i >> 6)) * 64 + (i & 63)];
        }
        __syncthreads();
#pragma unroll
        for (int kk = 0; kk < 16; kk++) {
            float4 a0 = *reinterpret_cast<const float4*>(&As[kk][r8 * 8]);
            float4 a1 = *reinterpret_cast<const float4*>(&As[kk][r8 * 8 + 4]);
            float4 w0 = *reinterpret_cast<const float4*>(&Ws[kk][c8 * 8]);
            float4 w1 = *reinterpret_cast<const float4*>(&Ws[kk][c8 * 8 + 4]);
            float ar[8] = {a0.x, a0.y, a0.z, a0.w, a1.x, a1.y, a1.z, a1.w};
            float wr[8] = {w0.x, w0.y, w0.z, w0.w, w1.x, w1.y, w1.z, w1.w};
#pragma unroll
            for (int i = 0; i < 8; i++)
#pragma unroll
                for (int j = 0; j < 8; j++) acc[i][j] += ar[i] * wr[j];
        }
        __syncthreads();
    }
#pragma unroll
    for (int i = 0; i < 8; i++) {
        int gr = rowBase + r8 * 8 + i;
        if (gr < M) {
#pragma unroll
            for (int j = 0; j < 8; j += 2) {
                float v0 = acc[i][j] + b[c8 * 8 + j];
                float v1 = acc[i][j + 1] + b[c8 * 8 + j + 1];
                v0 = v0 > 0.f ? v0 : 0.f;
                v1 = v1 > 0.f ? v1 : 0.f;
                C[(size_t)gr * 64 + c8 * 8 + j] = v0;
                C[(size_t)gr * 64 + c8 * 8 + j + 1] = v1;
                C16[(size_t)gr * 32 + (c8 * 8 + j) / 2] = __floats2half2_rn(v0, v1);
            }
        }
    }
}

// ------------------------- CSR build ----------------------------------------
__global__ void zero_deg_kernel() {
    int i = blockIdx.x * blockDim.x + threadIdx.x;
    if (i < NA) g_deg_ap[i] = 0;
    if (i < NP) { g_deg_pa[i] = 0; g_deg_pp[i] = 0; }
}

__global__ void hist_all_kernel(const int* __restrict__ s_ap, const int* __restrict__ s_pa,
                                const int* __restrict__ s_pp, int Eap, int Epa, int Epp) {
    int i = blockIdx.x * blockDim.x + threadIdx.x;
    int tot = Eap + Epa + Epp;
    if (i >= tot) return;
    if (i < Eap) atomicAdd(&g_deg_ap[s_ap[i]], 1);
    else if (i < Eap + Epa) atomicAdd(&g_deg_pa[s_pa[i - Eap]], 1);
    else atomicAdd(&g_deg_pp[s_pp[i - Eap - Epa]], 1);
}

__device__ void scan_block(const int* __restrict__ deg, int* __restrict__ rp,
                           int* __restrict__ cur, int n) {
    __shared__ int carry;
    __shared__ int wsum[32];
    if (threadIdx.x == 0) carry = 0;
    __syncthreads();
    int lane = threadIdx.x & 31, wid = threadIdx.x >> 5;
    for (int base = 0; base < n; base += 1024) {
        int i = base + threadIdx.x;
        int v = (i < n) ? deg[i] : 0;
        int x = v;
#pragma unroll
        for (int o = 1; o < 32; o <<= 1) {
            int y = __shfl_up_sync(0xffffffffu, x, o);
            if (lane >= o) x += y;
        }
        if (lane == 31) wsum[wid] = x;
        __syncthreads();
        if (wid == 0) {
            int sv = wsum[lane];
#pragma unroll
            for (int o = 1; o < 32; o <<= 1) {
                int y = __shfl_up_sync(0xffffffffu, sv, o);
                if (lane >= o) sv += y;
            }
            wsum[lane] = sv;
        }
        __syncthreads();
        int excl = carry + x - v + ((wid > 0) ? wsum[wid - 1] : 0);
        if (i < n) { rp[i] = excl; cur[i] = excl; }
        int tot = wsum[31];
        __syncthreads();
        if (threadIdx.x == 0) carry += tot;
        __syncthreads();
    }
    if (threadIdx.x == 0) rp[n] = carry;
}

__global__ void scan_all_kernel() {
    if (blockIdx.x == 0) scan_block(g_deg_ap, g_rp_ap, g_cur_ap, NA);
    else if (blockIdx.x == 1) scan_block(g_deg_pa, g_rp_pa, g_cur_pa, NP);
    else scan_block(g_deg_pp, g_rp_pp, g_cur_pp, NP);
}

__global__ void scatter_all_kernel(const int* __restrict__ s_ap, const int* __restrict__ t_ap,
                                   const int* __restrict__ s_pa, const int* __restrict__ t_pa,
                                   const int* __restrict__ s_pp, const int* __restrict__ t_pp,
                                   int Eap, int Epa, int Epp) {
    int i = blockIdx.x * blockDim.x + threadIdx.x;
    int tot = Eap + Epa + Epp;
    if (i >= tot) return;
    if (i < Eap) {
        int pos = atomicAdd(&g_cur_ap[s_ap[i]], 1);
        g_ct_ap[pos] = t_ap[i];
    } else if (i < Eap + Epa) {
        int j = i - Eap;
        int pos = atomicAdd(&g_cur_pa[s_pa[j]], 1);
        g_ct_pa[pos] = t_pa[j];
    } else {
        int j = i - Eap - Epa;
        int pos = atomicAdd(&g_cur_pp[s_pp[j]], 1);
        g_ct_pp[pos] = t_pp[j];
    }
}

// ------------------------- scalar precompute ---------------------------------
__device__ __forceinline__ float warp_red(float s) {
#pragma unroll
    for (int o = 16; o; o >>= 1) s += __shfl_xor_sync(0xffffffffu, s, o);
    return s;
}

// source-side x1/w2 for all hops, both node types (x is fixed per hop)
__global__ void src_all_kernel(const float* __restrict__ xa, const float* __restrict__ xp,
                               const float* __restrict__ a1ap, const float* __restrict__ a2ap,
                               const float* __restrict__ a1pa, const float* __restrict__ a2pa,
                               const float* __restrict__ a1pp, const float* __restrict__ a2pp) {
    int w = (blockIdx.x * blockDim.x + threadIdx.x) >> 5;
    int lane = threadIdx.x & 31;
    if (w < NA) {
        const float* xr = xa + (size_t)w * HH;
        float v0 = xr[lane], v1 = xr[lane + 32];
#pragma unroll
        for (int i = 0; i < NHOP; i++) {
            float s1 = warp_red(v0 * a1ap[i * HH + lane] + v1 * a1ap[i * HH + lane + 32]);
            float s2 = warp_red(v0 * a2ap[i * HH + lane] + v1 * a2ap[i * HH + lane + 32]);
            if (lane == 0) {
                g_x1_ap[i * NA + w] = s1;
                float z = s1 + s2;
                z = z >= 0.f ? z : 0.2f * z;
                g_w2_ap[i * NA + w] = __expf(z);
            }
        }
    } else if (w < NA + NP) {
        int n = w - NA;
        const float* xr = xp + (size_t)n * HH;
        float v0 = xr[lane], v1 = xr[lane + 32];
#pragma unroll
        for (int i = 0; i < NHOP; i++) {
            float s1 = warp_red(v0 * a1pa[i * HH + lane] + v1 * a1pa[i * HH + lane + 32]);
            float s2 = warp_red(v0 * a2pa[i * HH + lane] + v1 * a2pa[i * HH + lane + 32]);
            float s3 = warp_red(v0 * a1pp[i * HH + lane] + v1 * a1pp[i * HH + lane + 32]);
            float s4 = warp_red(v0 * a2pp[i * HH + lane] + v1 * a2pp[i * HH + lane + 32]);
            if (lane == 0) {
                g_x1_pa[i * NP + n] = s1;
                float z = s1 + s2;
                z = z >= 0.f ? z : 0.2f * z;
                g_w2_pa[i * NP + n] = __expf(z);
                g_x1_pp[i * NP + n] = s3;
                float z2 = s3 + s4;
                z2 = z2 >= 0.f ? z2 : 0.2f * z2;
                g_w2_pp[i * NP + n] = __expf(z2);
            }
        }
    }
}

// target-side h1 for one hop (h changes each hop). Reads fp16 tables.
// Paired layout: lane handles elements (2*lane, 2*lane+1).
__global__ void tgt_all_kernel(const __half2* __restrict__ ha16,
                               const __half2* __restrict__ hp16,
                               const float* __restrict__ a2ap,
                               const float* __restrict__ a2pa,
                               const float* __restrict__ a2pp) {
    int w = (blockIdx.x * blockDim.x + threadIdx.x) >> 5;
    int lane = threadIdx.x & 31;
    if (w < NP) {
        float2 f = __half22float2(hp16[(size_t)w * 32 + lane]);
        float s1 = warp_red(f.x * a2ap[2 * lane] + f.y * a2ap[2 * lane + 1]);
        float s2 = warp_red(f.x * a2pp[2 * lane] + f.y * a2pp[2 * lane + 1]);
        if (lane == 0) { g_h1_ap[w] = s1; g_h1_pp[w] = s2; }
    } else if (w < NP + NA) {
        int n = w - NP;
        float2 f = __half22float2(ha16[(size_t)n * 32 + lane]);
        float s = warp_red(f.x * a2pa[2 * lane] + f.y * a2pa[2 * lane + 1]);
        if (lane == 0) g_h1_pa[n] = s;
    }
}

// ------------------------- aggregation --------------------------------------
__device__ __forceinline__ float eluf(float v) { return v > 0.f ? v : expm1f(v); }

// Warp-cooperative accumulation for one relation of one source node.
// fp16 gathers (4B/lane), 4 edges per inner iter, 4 independent acc pairs.
__device__ __forceinline__ float2 agg_rel16(int lane, int beg, int end,
                                            const int* __restrict__ ct,
                                            const __half2* __restrict__ ht2,
                                            float x1s, const float* __restrict__ h1,
                                            float& wsum) {
    float2 a0 = {0.f, 0.f}, a1 = {0.f, 0.f}, a2 = {0.f, 0.f}, a3 = {0.f, 0.f};
    for (int j0 = beg; j0 < end; j0 += 32) {
        int j = j0 + lane;
        float wv = 0.f;
        int t = 0;
        if (j < end) {
            t = ct[j];
            float z = x1s + h1[t];
            z = z >= 0.f ? z : 0.2f * z;
            wv = __expf(z);
            wsum += wv;
        }
        int cnt = min(32, end - j0);
        int k = 0;
        for (; k + 4 <= cnt; k += 4) {
            float w0 = __shfl_sync(0xffffffffu, wv, k);
            float w1 = __shfl_sync(0xffffffffu, wv, k + 1);
            float w2 = __shfl_sync(0xffffffffu, wv, k + 2);
            float w3 = __shfl_sync(0xffffffffu, wv, k + 3);
            int t0 = __shfl_sync(0xffffffffu, t, k);
            int t1 = __shfl_sync(0xffffffffu, t, k + 1);
            int t2 = __shfl_sync(0xffffffffu, t, k + 2);
            int t3 = __shfl_sync(0xffffffffu, t, k + 3);
            float2 v0 = __half22float2(ht2[(size_t)t0 * 32 + lane]);
            float2 v1 = __half22float2(ht2[(size_t)t1 * 32 + lane]);
            float2 v2 = __half22float2(ht2[(size_t)t2 * 32 + lane]);
            float2 v3 = __half22float2(ht2[(size_t)t3 * 32 + lane]);
            a0.x += w0 * v0.x; a0.y += w0 * v0.y;
            a1.x += w1 * v1.x; a1.y += w1 * v1.y;
            a2.x += w2 * v2.x; a2.y += w2 * v2.y;
            a3.x += w3 * v3.x; a3.y += w3 * v3.y;
        }
        for (; k < cnt; k++) {
            float wk = __shfl_sync(0xffffffffu, wv, k);
            int tk = __shfl_sync(0xffffffffu, t, k);
            float2 vk = __half22float2(ht2[(size_t)tk * 32 + lane]);
            a0.x += wk * vk.x; a0.y += wk * vk.y;
        }
    }
    float2 r;
    r.x = (a0.x + a1.x) + (a2.x + a3.x);
    r.y = (a0.y + a1.y) + (a2.y + a3.y);
    return r;
}

__global__ void __launch_bounds__(256) agg_a_kernel(
        const int* __restrict__ rp, const int* __restrict__ ct,
        const float* __restrict__ x, const __half2* __restrict__ ht,
        const float* __restrict__ x1, const float* __restrict__ h1,
        const float* __restrict__ w2,
        __half2* __restrict__ out, int n) {
    int wrp = (blockIdx.x * blockDim.x + threadIdx.x) >> 5;
    if (wrp >= n) return;
    int lane = threadIdx.x & 31;
    float x1s = x1[wrp];
    int beg = rp[wrp], end = rp[wrp + 1];
    float wsum = 0.f;
    float2 acc = agg_rel16(lane, beg, end, ct, ht, x1s, h1, wsum);
    wsum = warp_red(wsum);
    float w2s = w2[wrp];
    float inv = 1.f / (wsum + w2s);
    float2 xv = reinterpret_cast<const float2*>(x)[(size_t)wrp * 32 + lane];
    float o0 = eluf((acc.x + w2s * xv.x) * inv);
    float o1 = eluf((acc.y + w2s * xv.y) * inv);
    out[(size_t)wrp * 32 + lane] = __floats2half2_rn(o0, o1);
}

__global__ void __launch_bounds__(256) agg_p_kernel(
        const int* __restrict__ rp1, const int* __restrict__ ct1,
        const int* __restrict__ rp2, const int* __restrict__ ct2,
        const float* __restrict__ xp,
        const __half2* __restrict__ ha, const __half2* __restrict__ hp,
        const float* __restrict__ x1_1, const float* __restrict__ h1_1,
        const float* __restrict__ w2_1,
        const float* __restrict__ x1_2, const float* __restrict__ h1_2,
        const float* __restrict__ w2_2,
        __half2* __restrict__ out, int n) {
    int wrp = (blockIdx.x * blockDim.x + threadIdx.x) >> 5;
    if (wrp >= n) return;
    int lane = threadIdx.x & 31;
    float2 xv = reinterpret_cast<const float2*>(xp)[(size_t)wrp * 32 + lane];

    float ws1 = 0.f;
    float2 accA = agg_rel16(lane, rp1[wrp], rp1[wrp + 1], ct1, ha, x1_1[wrp], h1_1, ws1);
    ws1 = warp_red(ws1);
    float w2a = w2_1[wrp];
    float inv1 = 1.f / (ws1 + w2a);
    float r10 = (accA.x + w2a * xv.x) * inv1;
    float r11 = (accA.y + w2a * xv.y) * inv1;

    float ws2 = 0.f;
    float2 accB = agg_rel16(lane, rp2[wrp], rp2[wrp + 1], ct2, hp, x1_2[wrp], h1_2, ws2);
    ws2 = warp_red(ws2);
    float w2b = w2_2[wrp];
    float inv2 = 1.f / (ws2 + w2b);
    float r20 = (accB.x + w2b * xv.x) * inv2;
    float r21 = (accB.y + w2b * xv.y) * inv2;

    float o0 = eluf(0.5f * (r10 + r20));
    float o1 = eluf(0.5f * (r11 + r21));
    out[(size_t)wrp * 32 + lane] = __floats2half2_rn(o0, o1);
}

// ------------------------- output projection ---------------------------------
__global__ void fc2_kernel(const __half2* __restrict__ h, const float* __restrict__ W,
                           const float* __restrict__ b, float* __restrict__ out, int n) {
    __shared__ float Ws[HH * NOUT];
    __shared__ float bs[NOUT];
    for (int i = threadIdx.x; i < HH * NOUT; i += blockDim.x) Ws[i] = W[i];
    if (threadIdx.x < NOUT) bs[threadIdx.x] = b[threadIdx.x];
    __syncthreads();
    int idx = blockIdx.x * blockDim.x + threadIdx.x;
    int node = idx >> 4, col = idx & 15;
    if (node >= n) return;
    const __half2* hr = h + (size_t)node * 32;
    float s = bs[col];
#pragma unroll
    for (int k = 0; k < 32; k++) {
        float2 f = __half22float2(hr[k]);
        s += f.x * Ws[(2 * k) * NOUT + col] + f.y * Ws[(2 * k + 1) * NOUT + col];
    }
    out[(size_t)node * NOUT + col] = s;
}

// ------------------------- host orchestration --------------------------------
extern "C" void kernel_launch(void* const* d_in, const int* in_sizes, int n_in,
                              void* d_out, int out_size) {
    const float* x_a = (const float*)d_in[0];
    const float* x_p = (const float*)d_in[1];
    const int* ap_s = (const int*)d_in[2];
    const int* ap_t = (const int*)d_in[3];
    const int* pa_s = (const int*)d_in[4];
    const int* pa_t = (const int*)d_in[5];
    const int* pp_s = (const int*)d_in[6];
    const int* pp_t = (const int*)d_in[7];
    const float* fc1_a_w = (const float*)d_in[8];
    const float* fc1_a_b = (const float*)d_in[9];
    const float* fc1_p_w = (const float*)d_in[10];
    const float* fc1_p_b = (const float*)d_in[11];
    const float* fc2_w = (const float*)d_in[12];
    const float* fc2_b = (const float*)d_in[13];
    const float* a1_ap = (const float*)d_in[14];
    const float* a2_ap = (const float*)d_in[15];
    const float* a1_pa = (const float*)d_in[16];
    const float* a2_pa = (const float*)d_in[17];
    const float* a1_pp = (const float*)d_in[18];
    const float* a2_pp = (const float*)d_in[19];
    float* out = (float*)d_out;

    int E_ap = in_sizes[2], E_pa = in_sizes[4], E_pp = in_sizes[6];
    if (E_ap > EMAX) E_ap = EMAX;
    if (E_pa > EMAX) E_pa = EMAX;
    if (E_pp > EMAX) E_pp = EMAX;
    int E_tot = E_ap + E_pa + E_pp;

    float *xa, *xp;
    cudaGetSymbolAddress((void**)&xa, g_xa);
    cudaGetSymbolAddress((void**)&xp, g_xp);
    __half2 *ha16A, *ha16B, *hp16A, *hp16B;
    cudaGetSymbolAddress((void**)&ha16A, g_ha16A);
    cudaGetSymbolAddress((void**)&ha16B, g_ha16B);
    cudaGetSymbolAddress((void**)&hp16A, g_hp16A);
    cudaGetSymbolAddress((void**)&hp16B, g_hp16B);

    int *rp_ap, *ct_ap, *rp_pa, *ct_pa, *rp_pp, *ct_pp;
    cudaGetSymbolAddress((void**)&rp_ap, g_rp_ap);
    cudaGetSymbolAddress((void**)&ct_ap, g_ct_ap);
    cudaGetSymbolAddress((void**)&rp_pa, g_rp_pa);
    cudaGetSymbolAddress((void**)&ct_pa, g_ct_pa);
    cudaGetSymbolAddress((void**)&rp_pp, g_rp_pp);
    cudaGetSymbolAddress((void**)&ct_pp, g_ct_pp);

    float *x1_ap, *w2_ap, *h1_ap, *x1_pa, *w2_pa, *h1_pa, *x1_pp, *w2_pp, *h1_pp;
    cudaGetSymbolAddress((void**)&x1_ap, g_x1_ap);
    cudaGetSymbolAddress((void**)&w2_ap, g_w2_ap);
    cudaGetSymbolAddress((void**)&h1_ap, g_h1_ap);
    cudaGetSymbolAddress((void**)&x1_pa, g_x1_pa);
    cudaGetSymbolAddress((void**)&w2_pa, g_w2_pa);
    cudaGetSymbolAddress((void**)&h1_pa, g_h1_pa);
    cudaGetSymbolAddress((void**)&x1_pp, g_x1_pp);
    cudaGetSymbolAddress((void**)&w2_pp, g_w2_pp);
    cudaGetSymbolAddress((void**)&h1_pp, g_h1_pp);

    // 1) CSR build
    zero_deg_kernel<<<(NP + 255) / 256, 256>>>();
    hist_all_kernel<<<(E_tot + 255) / 256, 256>>>(ap_s, pa_s, pp_s, E_ap, E_pa, E_pp);
    scan_all_kernel<<<3, 1024>>>();
    scatter_all_kernel<<<(E_tot + 255) / 256, 256>>>(ap_s, ap_t, pa_s, pa_t, pp_s, pp_t,
                                                     E_ap, E_pa, E_pp);

    // 2) input projections (fp32 x + fp16 initial h)
    proj_kernel<<<(NA + 255) / 256, 256>>>(x_a, fc1_a_w, fc1_a_b, xa, ha16A, NA, DA);
    proj_kernel<<<(NP + 255) / 256, 256>>>(x_p, fc1_p_w, fc1_p_b, xp, hp16A, NP, DP);

    // 3) source-side scalars for all hops at once
    src_all_kernel<<<((NA + NP) * 32 + 255) / 256, 256>>>(xa, xp, a1_ap, a2_ap,
                                                          a1_pa, a2_pa, a1_pp, a2_pp);

    // 4) hops
    const __half2* ha = ha16A;
    const __half2* hp = hp16A;
    const int WB = 8;  // warps per 256-thread block
    for (int i = 0; i < NHOP; i++) {
        __half2* hao = (i & 1) ? ha16A : ha16B;
        __half2* hpo = (i & 1) ? hp16A : hp16B;

        tgt_all_kernel<<<((NP + NA) * 32 + 255) / 256, 256>>>(ha, hp, a2_ap + i * HH,
                                                              a2_pa + i * HH, a2_pp + i * HH);
        agg_a_kernel<<<(NA + WB - 1) / WB, 256>>>(rp_ap, ct_ap, xa, hp,
                                                  x1_ap + i * NA, h1_ap, w2_ap + i * NA,
                                                  hao, NA);
        agg_p_kernel<<<(NP + WB - 1) / WB, 256>>>(rp_pa, ct_pa, rp_pp, ct_pp, xp, ha, hp,
                                                  x1_pa + i * NP, h1_pa, w2_pa + i * NP,
                                                  x1_pp + i * NP, h1_pp, w2_pp + i * NP,
                                                  hpo, NP);
        ha = hao;
        hp = hpo;
    }

    // 5) output projection (reads final fp16 h_a)
    fc2_kernel<<<(NA * NOUT + 255) / 256, 256>>>(ha, fc2_w, fc2_b, out, NA);
}